// round 9
// baseline (speedup 1.0000x reference)
#include <cuda_runtime.h>
#include <cuda_bf16.h>
#include <math.h>

#define MB   256
#define TX   256
#define FDIM 128
#define NA   256
#define NS   512
#define VOC  1024
#define AH   10
#define TYD  10

// ---------------- scratch ----------------
__device__ float    g_gin[2][TX][MB][4 * NA];   // col c = g*256 + u
__device__ float    g_a[TX][MB][NS];
__device__ unsigned g_abf[TX][MB][NS / 2];      // bf16x2-packed copy of g_a
__device__ float    g_hT[2][2][NA][MB];         // [dir][t&1][u][m] double-buffered
__device__ float    g_Ea[MB][TX][AH];
__device__ float    g_ctx[MB][NS];
__device__ float    g_sbuf[2][MB][NS];
__device__ float    g_cdec[MB][NS];
__device__ unsigned g_bar[8][32];               // padded: one counter per 128B

__device__ __forceinline__ float sigf(float x) { return 1.f / (1.f + expf(-x)); }
__device__ __forceinline__ float fsig(float x) { return __fdividef(1.f, 1.f + __expf(-x)); }
__device__ __forceinline__ float ftanh(float x) { return 1.f - __fdividef(2.f, __expf(2.f * x) + 1.f); }

#define FMA2(acc, a, b) asm("fma.rn.f32x2 %0, %1, %2, %0;" : "+l"(acc) : "l"(a), "l"(b))
#define PACK2(d, lo, hi) asm("mov.b64 %0, {%1, %2};" : "=l"(d) : "f"(lo), "f"(hi))
#define UNPACK2(lo, hi, v) asm("mov.b64 {%0, %1}, %2;" : "=f"(lo), "=f"(hi) : "l"(v))

__global__ void zero_bar_kernel()
{
    int i = threadIdx.x;
    if (i < 256) ((unsigned*)g_bar)[i] = 0u;
}

__global__ void init_dec_kernel()
{
    int i = blockIdx.x * 256 + threadIdx.x;
    if (i < MB * NS) {
        (&g_sbuf[0][0][0])[i] = 0.f;
        (&g_cdec[0][0])[i] = 0.f;
    }
}

// ---------------- encoder input projection (f32x2): Gin = X @ Wih^T + b ----------------
__global__ void xproj_kernel(const float* __restrict__ X,
                             const float* __restrict__ Wf, const float* __restrict__ bf,
                             const float* __restrict__ Wb, const float* __restrict__ bb)
{
    int d = blockIdx.z;
    const float* W    = d ? Wb : Wf;
    const float* bias = d ? bb : bf;
    int col0 = blockIdx.x * 64;
    int row0 = blockIdx.y * 64;
    int t  = row0 >> 8;
    int m0 = row0 & 255;
    int xt = d ? (TX - 1 - t) : t;

    __shared__ float As[16][68];
    __shared__ float Bs[16][132];
    int tid = threadIdx.x;
    int ry = tid >> 4, rx = tid & 15;

    unsigned long long acc2[2][4];
    #pragma unroll
    for (int p = 0; p < 2; p++)
        #pragma unroll
        for (int j = 0; j < 4; j++) acc2[p][j] = 0ull;

    int lr = tid >> 2;
    int lk4 = (tid & 3) * 4;

    for (int k0 = 0; k0 < FDIM; k0 += 16) {
        float4 av = *(const float4*)(X + ((size_t)(m0 + lr) * TX + xt) * FDIM + k0 + lk4);
        As[lk4 + 0][lr] = av.x; As[lk4 + 1][lr] = av.y;
        As[lk4 + 2][lr] = av.z; As[lk4 + 3][lr] = av.w;
        float4 bv = *(const float4*)(W + (size_t)(col0 + lr) * FDIM + k0 + lk4);
        float vv[4] = {bv.x, bv.y, bv.z, bv.w};
        #pragma unroll
        for (int j = 0; j < 4; j++)
            *(float2*)&Bs[lk4 + j][lr * 2] = make_float2(vv[j], vv[j]);
        __syncthreads();
        #pragma unroll
        for (int kk = 0; kk < 16; kk++) {
            ulonglong2 ap = *(const ulonglong2*)&As[kk][ry * 4];
            ulonglong2 w0 = *(const ulonglong2*)&Bs[kk][rx * 8];
            ulonglong2 w1 = *(const ulonglong2*)&Bs[kk][rx * 8 + 4];
            FMA2(acc2[0][0], ap.x, w0.x); FMA2(acc2[0][1], ap.x, w0.y);
            FMA2(acc2[0][2], ap.x, w1.x); FMA2(acc2[0][3], ap.x, w1.y);
            FMA2(acc2[1][0], ap.y, w0.x); FMA2(acc2[1][1], ap.y, w0.y);
            FMA2(acc2[1][2], ap.y, w1.x); FMA2(acc2[1][3], ap.y, w1.y);
        }
        __syncthreads();
    }

    int c = col0 + rx * 4;
    float4 bv = *(const float4*)&bias[c];
    float r0[4], r1[4], r2[4], r3[4];
    UNPACK2(r0[0], r1[0], acc2[0][0]); UNPACK2(r0[1], r1[1], acc2[0][1]);
    UNPACK2(r0[2], r1[2], acc2[0][2]); UNPACK2(r0[3], r1[3], acc2[0][3]);
    UNPACK2(r2[0], r3[0], acc2[1][0]); UNPACK2(r2[1], r3[1], acc2[1][1]);
    UNPACK2(r2[2], r3[2], acc2[1][2]); UNPACK2(r2[3], r3[3], acc2[1][3]);
    float* o0 = &g_gin[d][t][m0 + ry * 4 + 0][c];
    float* o1 = &g_gin[d][t][m0 + ry * 4 + 1][c];
    float* o2 = &g_gin[d][t][m0 + ry * 4 + 2][c];
    float* o3 = &g_gin[d][t][m0 + ry * 4 + 3][c];
    *(float4*)o0 = make_float4(r0[0] + bv.x, r0[1] + bv.y, r0[2] + bv.z, r0[3] + bv.w);
    *(float4*)o1 = make_float4(r1[0] + bv.x, r1[1] + bv.y, r1[2] + bv.z, r1[3] + bv.w);
    *(float4*)o2 = make_float4(r2[0] + bv.x, r2[1] + bv.y, r2[2] + bv.z, r2[3] + bv.w);
    *(float4*)o3 = make_float4(r3[0] + bv.x, r3[1] + bv.y, r3[2] + bv.z, r3[3] + bv.w);
}

// ---------------- persistent recurrence ----------------
// R2 core geometry (128 thr, dup-W smem, 8m x 4g per thread) with:
//  - padded per-group barrier counters + red.release arrive / ld.acquire poll
//  - smem-staged epilogue -> coalesced hT / g_a / bf16 stores
//  - double-buffered hT
__global__ void __launch_bounds__(128, 1) lstm_all_kernel(const float* __restrict__ Whf,
                                                          const float* __restrict__ Whb)
{
    extern __shared__ float sm[];
    float* Ws = sm;                  // [256][128] = 128 KB (duplicated pairs)
    float* As = sm + 256 * 128;      // [256][64]  = 64 KB
    float* Hs = As + 256 * 64;       // [16][68]   = 4.25 KB staging

    int d = blockIdx.z;
    const float* W = d ? Whb : Whf;
    int u0 = blockIdx.x * 16;
    int m0 = blockIdx.y * 64;
    int tid = threadIdx.x;
    int ul = tid & 15, mg = tid >> 4;
    int u = u0 + ul;
    unsigned* barp = &g_bar[d * 4 + blockIdx.y][0];

    for (int idx = tid; idx < 64 * 64; idx += 128) {
        int r  = idx >> 6;
        int k4 = idx & 63;
        int uu = r >> 2, g = r & 3;
        float4 w4 = *(const float4*)&W[(size_t)(g * NA + u0 + uu) * NA + k4 * 4];
        float vv[4] = {w4.x, w4.y, w4.z, w4.w};
        #pragma unroll
        for (int j = 0; j < 4; j++)
            *(float2*)&Ws[(k4 * 4 + j) * 128 + r * 2] = make_float2(vv[j], vv[j]);
    }

    float c[8];
    #pragma unroll
    for (int i = 0; i < 8; i++) c[i] = 0.f;

    float rg[8][4];
    {
        const float* gb = &g_gin[d][0][0][0];
        #pragma unroll
        for (int mi = 0; mi < 8; mi++) {
            int m = m0 + mg * 8 + mi;
            #pragma unroll
            for (int g = 0; g < 4; g++)
                rg[mi][g] = gb[(size_t)m * 1024 + g * 256 + u];
        }
    }

    for (int t = 0; t < TX; t++) {
        // ---- As fill: h(t-1) from hT buffer (t-1)&1 (coalesced) ----
        if (t == 0) {
            float4 z = make_float4(0.f, 0.f, 0.f, 0.f);
            for (int idx = tid; idx < 4096; idx += 128)
                ((float4*)As)[idx] = z;
        } else {
            const float* hsrc = &g_hT[d][(t - 1) & 1][0][0];
            for (int idx = tid; idx < 4096; idx += 128) {
                int m4 = idx & 15;
                int k  = idx >> 4;
                float4 v = __ldcg((const float4*)&hsrc[(size_t)k * MB + m0 + m4 * 4]);
                *(float4*)&As[k * 64 + m4 * 4] = v;
            }
        }
        __syncthreads();

        unsigned long long acc2[4][4];
        #pragma unroll
        for (int p = 0; p < 4; p++)
            #pragma unroll
            for (int g = 0; g < 4; g++)
                PACK2(acc2[p][g], rg[2 * p][g], rg[2 * p + 1][g]);

        #pragma unroll 4
        for (int k = 0; k < NA; k++) {
            ulonglong2 aL = *(const ulonglong2*)&As[k * 64 + mg * 8];
            ulonglong2 aH = *(const ulonglong2*)&As[k * 64 + mg * 8 + 4];
            ulonglong2 wA = *(const ulonglong2*)&Ws[k * 128 + ul * 8];
            ulonglong2 wB = *(const ulonglong2*)&Ws[k * 128 + ul * 8 + 4];
            FMA2(acc2[0][0], aL.x, wA.x); FMA2(acc2[0][1], aL.x, wA.y);
            FMA2(acc2[0][2], aL.x, wB.x); FMA2(acc2[0][3], aL.x, wB.y);
            FMA2(acc2[1][0], aL.y, wA.x); FMA2(acc2[1][1], aL.y, wA.y);
            FMA2(acc2[1][2], aL.y, wB.x); FMA2(acc2[1][3], aL.y, wB.y);
            FMA2(acc2[2][0], aH.x, wA.x); FMA2(acc2[2][1], aH.x, wA.y);
            FMA2(acc2[2][2], aH.x, wB.x); FMA2(acc2[2][3], aH.x, wB.y);
            FMA2(acc2[3][0], aH.y, wA.x); FMA2(acc2[3][1], aH.y, wA.y);
            FMA2(acc2[3][2], aH.y, wB.x); FMA2(acc2[3][3], aH.y, wB.y);
        }

        // ---- gates + state; stage h into Hs[u][m] ----
        float hv[8];
        #pragma unroll
        for (int p = 0; p < 4; p++) {
            float i0, i1, f0, f1, g0, g1, o0, o1;
            UNPACK2(i0, i1, acc2[p][0]);
            UNPACK2(f0, f1, acc2[p][1]);
            UNPACK2(g0, g1, acc2[p][2]);
            UNPACK2(o0, o1, acc2[p][3]);
            {
                int e = 2 * p;
                float cn = fsig(f0) * c[e] + fsig(i0) * ftanh(g0);
                c[e] = cn;
                hv[e] = fsig(o0) * ftanh(cn);
            }
            {
                int e = 2 * p + 1;
                float cn = fsig(f1) * c[e] + fsig(i1) * ftanh(g1);
                c[e] = cn;
                hv[e] = fsig(o1) * ftanh(cn);
            }
        }
        #pragma unroll
        for (int e = 0; e < 8; e++)
            Hs[ul * 68 + mg * 8 + e] = hv[e];
        __syncthreads();

        // ---- cooperative coalesced writes from Hs ----
        int tw = d ? (TX - 1 - t) : t;
        {
            float* hdst = &g_hT[d][t & 1][0][0];
            #pragma unroll
            for (int i = 0; i < 2; i++) {        // hT[u][m]: 16u x 64m
                int idx = tid + 128 * i;
                int uu = idx >> 4, m4 = idx & 15;
                float4 v = *(float4*)&Hs[uu * 68 + m4 * 4];
                *(float4*)&hdst[(size_t)(u0 + uu) * MB + m0 + m4 * 4] = v;
            }
            #pragma unroll
            for (int i = 0; i < 2; i++) {        // g_a[m][u]: 64m x 4 u-quads
                int idx = tid + 128 * i;
                int mm = idx >> 2, q = idx & 3;
                float4 v = make_float4(Hs[(q * 4 + 0) * 68 + mm],
                                       Hs[(q * 4 + 1) * 68 + mm],
                                       Hs[(q * 4 + 2) * 68 + mm],
                                       Hs[(q * 4 + 3) * 68 + mm]);
                *(float4*)&g_a[tw][m0 + mm][d * NA + u0 + q * 4] = v;
            }
            {                                     // bf16 pack: 64m x 2 halves
                int mm = tid >> 1, half = tid & 1;
                unsigned w[4];
                #pragma unroll
                for (int j = 0; j < 4; j++) {
                    float f0 = Hs[(half * 8 + 2 * j + 0) * 68 + mm];
                    float f1 = Hs[(half * 8 + 2 * j + 1) * 68 + mm];
                    __nv_bfloat162 b = __float22bfloat162_rn(make_float2(f0, f1));
                    w[j] = *(unsigned*)&b;
                }
                *(uint4*)&g_abf[tw][m0 + mm][(d * NA + u0) / 2 + half * 4] =
                    make_uint4(w[0], w[1], w[2], w[3]);
            }
        }

        if (t + 1 < TX) {
            // prefetch gin(t+1)
            const float* gb = &g_gin[d][t + 1][0][0];
            #pragma unroll
            for (int mi = 0; mi < 8; mi++) {
                int m = m0 + mg * 8 + mi;
                #pragma unroll
                for (int g = 0; g < 4; g++)
                    rg[mi][g] = gb[(size_t)m * 1024 + g * 256 + u];
            }
            __syncthreads();
            if (tid == 0) {
                asm volatile("red.release.gpu.global.add.u32 [%0], %1;"
                             :: "l"(barp), "r"(1u) : "memory");
                unsigned tgt = 16u * (unsigned)(t + 1);
                unsigned v;
                do {
                    asm volatile("ld.acquire.gpu.global.u32 %0, [%1];"
                                 : "=r"(v) : "l"(barp) : "memory");
                } while (v < tgt);
            }
            __syncthreads();
        }
    }
}

// ---------------- hoisted attention energies: Ea = a @ W1a^T ----------------
__global__ void ea_kernel(const float* __restrict__ W1)
{
    __shared__ float W1t[512][AH];
    int tid = threadIdx.x;
    for (int i = tid; i < 512 * AH; i += 256) {
        int h = i / 512, k = i - h * 512;
        W1t[k][h] = W1[h * 1024 + k];
    }
    __syncthreads();
    int r = blockIdx.x * 256 + tid;
    const float* arow = &g_a[0][0][0] + (size_t)r * NS;
    float e[AH] = {};
    for (int k = 0; k < 512; k += 4) {
        float4 av = *(const float4*)(arow + k);
        #pragma unroll
        for (int h = 0; h < AH; h++)
            e[h] += av.x * W1t[k][h] + av.y * W1t[k + 1][h]
                  + av.z * W1t[k + 2][h] + av.w * W1t[k + 3][h];
    }
    int tt = r >> 8;
    int m = r & 255;
    float* eo = &g_Ea[m][tt][0];
    #pragma unroll
    for (int h = 0; h < AH; h++) eo[h] = e[h];
}

// ---------------- attention ----------------
__global__ void attention_kernel(const float* __restrict__ W1, const float* __restrict__ b1,
                                 const float* __restrict__ W2, const float* __restrict__ b2,
                                 int pin)
{
    int m = blockIdx.x;
    int tid = threadIdx.x;
    int lane = tid & 31, warp = tid >> 5;
    __shared__ float Ss[NS];
    __shared__ float EsSh[AH];
    __shared__ float alpha[TX];
    __shared__ float red[8];
    __shared__ float sh_mx, sh_sum;

    const float* s_in = &g_sbuf[pin][m][0];
    Ss[tid] = s_in[tid];
    Ss[tid + 256] = s_in[tid + 256];
    __syncthreads();

    for (int h = warp; h < AH; h += 8) {
        float p = 0.f;
        for (int k = lane; k < NS; k += 32)
            p += Ss[k] * W1[h * 1024 + 512 + k];
        #pragma unroll
        for (int o = 16; o; o >>= 1) p += __shfl_xor_sync(0xffffffffu, p, o);
        if (lane == 0) EsSh[h] = p + b1[h];
    }
    __syncthreads();

    float sc = b2[0];
    {
        const float* ea = &g_Ea[m][tid][0];
        #pragma unroll
        for (int h = 0; h < AH; h++)
            sc += W2[h] * tanhf(ea[h] + EsSh[h]);
    }
    sc = fmaxf(sc, 0.f);

    float v = sc;
    #pragma unroll
    for (int o = 16; o; o >>= 1) v = fmaxf(v, __shfl_xor_sync(0xffffffffu, v, o));
    if (lane == 0) red[warp] = v;
    __syncthreads();
    if (tid == 0) {
        float mx = red[0];
        #pragma unroll
        for (int i = 1; i < 8; i++) mx = fmaxf(mx, red[i]);
        sh_mx = mx;
    }
    __syncthreads();
    float ev = expf(sc - sh_mx);
    float sv = ev;
    #pragma unroll
    for (int o = 16; o; o >>= 1) sv += __shfl_xor_sync(0xffffffffu, sv, o);
    if (lane == 0) red[warp] = sv;
    __syncthreads();
    if (tid == 0) {
        float s = 0.f;
        #pragma unroll
        for (int i = 0; i < 8; i++) s += red[i];
        sh_sum = s;
    }
    __syncthreads();
    alpha[tid] = ev / sh_sum;
    __syncthreads();

    const unsigned* ab = &g_abf[0][m][0] + tid;
    float ax = 0.f, ay = 0.f;
    #pragma unroll 8
    for (int t2 = 0; t2 < TX; t2++) {
        unsigned p = ab[(size_t)t2 * MB * (NS / 2)];
        __nv_bfloat162 b2v = *(__nv_bfloat162*)&p;
        float2 vv = __bfloat1622float2(b2v);
        float al = alpha[t2];
        ax += al * vv.x;
        ay += al * vv.y;
    }
    g_ctx[m][2 * tid + 0] = ax;
    g_ctx[m][2 * tid + 1] = ay;
}

// ---------------- decoder LSTM cell (f32x2) ----------------
__global__ void dec_cell_kernel(const float* __restrict__ Wih, const float* __restrict__ Whh,
                                const float* __restrict__ bc, int pin)
{
    int u0 = blockIdx.x * 16;
    int m0 = blockIdx.y * 64;
    int tid = threadIdx.x;
    int ul = tid & 15, mg = tid >> 4;
    int u = u0 + ul;

    __shared__ float As[32][68];
    __shared__ float Ws[32][132];

    unsigned long long acc2[2][4];
    #pragma unroll
    for (int g = 0; g < 4; g++) {
        float b = bc[g * NS + u];
        PACK2(acc2[0][g], b, b);
        acc2[1][g] = acc2[0][g];
    }

    for (int ph = 0; ph < 2; ph++) {
        const float* Arow = ph ? &g_sbuf[pin][0][0] : &g_ctx[0][0];
        const float* W = ph ? Whh : Wih;
        for (int k0 = 0; k0 < NS; k0 += 32) {
            #pragma unroll
            for (int i = 0; i < 2; i++) {
                int lin = tid + 256 * i;
                int mm = lin >> 3, kq = lin & 7;
                float4 f = *(const float4*)&Arow[(size_t)(m0 + mm) * NS + k0 + kq * 4];
                As[kq * 4 + 0][mm] = f.x; As[kq * 4 + 1][mm] = f.y;
                As[kq * 4 + 2][mm] = f.z; As[kq * 4 + 3][mm] = f.w;
            }
            #pragma unroll
            for (int i = 0; i < 2; i++) {
                int lin = tid + 256 * i;
                int r = lin >> 3, kq = lin & 7;
                int uu = r >> 2, g = r & 3;
                float4 f = *(const float4*)&W[(size_t)(g * NS + u0 + uu) * NS + k0 + kq * 4];
                float vv[4] = {f.x, f.y, f.z, f.w};
                #pragma unroll
                for (int j = 0; j < 4; j++)
                    *(float2*)&Ws[kq * 4 + j][r * 2] = make_float2(vv[j], vv[j]);
            }
            __syncthreads();
            #pragma unroll 8
            for (int kk = 0; kk < 32; kk++) {
                ulonglong2 ap = *(const ulonglong2*)&As[kk][mg * 4];
                ulonglong2 wA = *(const ulonglong2*)&Ws[kk][ul * 8];
                ulonglong2 wB = *(const ulonglong2*)&Ws[kk][ul * 8 + 4];
                FMA2(acc2[0][0], ap.x, wA.x); FMA2(acc2[0][1], ap.x, wA.y);
                FMA2(acc2[0][2], ap.x, wB.x); FMA2(acc2[0][3], ap.x, wB.y);
                FMA2(acc2[1][0], ap.y, wA.x); FMA2(acc2[1][1], ap.y, wA.y);
                FMA2(acc2[1][2], ap.y, wB.x); FMA2(acc2[1][3], ap.y, wB.y);
            }
            __syncthreads();
        }
    }

    #pragma unroll
    for (int p = 0; p < 2; p++) {
        float i0, i1, f0, f1, g0, g1, o0, o1;
        UNPACK2(i0, i1, acc2[p][0]);
        UNPACK2(f0, f1, acc2[p][1]);
        UNPACK2(g0, g1, acc2[p][2]);
        UNPACK2(o0, o1, acc2[p][3]);
        {
            int m = m0 + mg * 4 + 2 * p;
            float co = g_cdec[m][u];
            float cn = sigf(f0) * co + sigf(i0) * tanhf(g0);
            g_cdec[m][u] = cn;
            g_sbuf[1 - pin][m][u] = sigf(o0) * tanhf(cn);
        }
        {
            int m = m0 + mg * 4 + 2 * p + 1;
            float co = g_cdec[m][u];
            float cn = sigf(f1) * co + sigf(i1) * tanhf(g1);
            g_cdec[m][u] = cn;
            g_sbuf[1 - pin][m][u] = sigf(o1) * tanhf(cn);
        }
    }
}

// ---------------- output projection (f32x2) ----------------
__global__ void fc_kernel(const float* __restrict__ Wfc, const float* __restrict__ bfc,
                          float* __restrict__ outp, int ps, int ty)
{
    int col0 = blockIdx.x * 64;
    int m0 = blockIdx.y * 64;
    int tid = threadIdx.x;
    int ry = tid >> 4, rx = tid & 15;

    __shared__ float As[16][68];
    __shared__ float Bs[16][132];

    unsigned long long acc2[2][4];
    #pragma unroll
    for (int p = 0; p < 2; p++)
        #pragma unroll
        for (int j = 0; j < 4; j++) acc2[p][j] = 0ull;

    int lr = tid >> 2;
    int lk4 = (tid & 3) * 4;
    const float* S = &g_sbuf[ps][0][0];

    for (int k0 = 0; k0 < NS; k0 += 16) {
        float4 av = *(const float4*)(S + (size_t)(m0 + lr) * NS + k0 + lk4);
        As[lk4 + 0][lr] = av.x; As[lk4 + 1][lr] = av.y;
        As[lk4 + 2][lr] = av.z; As[lk4 + 3][lr] = av.w;
        float4 bv = *(const float4*)(Wfc + (size_t)(col0 + lr) * NS + k0 + lk4);
        float vv[4] = {bv.x, bv.y, bv.z, bv.w};
        #pragma unroll
        for (int j = 0; j < 4; j++)
            *(float2*)&Bs[lk4 + j][lr * 2] = make_float2(vv[j], vv[j]);
        __syncthreads();
        #pragma unroll
        for (int kk = 0; kk < 16; kk++) {
            ulonglong2 ap = *(const ulonglong2*)&As[kk][ry * 4];
            ulonglong2 w0 = *(const ulonglong2*)&Bs[kk][rx * 8];
            ulonglong2 w1 = *(const ulonglong2*)&Bs[kk][rx * 8 + 4];
            FMA2(acc2[0][0], ap.x, w0.x); FMA2(acc2[0][1], ap.x, w0.y);
            FMA2(acc2[0][2], ap.x, w1.x); FMA2(acc2[0][3], ap.x, w1.y);
            FMA2(acc2[1][0], ap.y, w0.x); FMA2(acc2[1][1], ap.y, w0.y);
            FMA2(acc2[1][2], ap.y, w1.x); FMA2(acc2[1][3], ap.y, w1.y);
        }
        __syncthreads();
    }

    int c = col0 + rx * 4;
    float4 bv = *(const float4*)&bfc[c];
    float r0[4], r1[4], r2[4], r3[4];
    UNPACK2(r0[0], r1[0], acc2[0][0]); UNPACK2(r0[1], r1[1], acc2[0][1]);
    UNPACK2(r0[2], r1[2], acc2[0][2]); UNPACK2(r0[3], r1[3], acc2[0][3]);
    UNPACK2(r2[0], r3[0], acc2[1][0]); UNPACK2(r2[1], r3[1], acc2[1][1]);
    UNPACK2(r2[2], r3[2], acc2[1][2]); UNPACK2(r2[3], r3[3], acc2[1][3]);
    int mA = m0 + ry * 4;
    float* o0 = &outp[((size_t)(mA + 0) * TYD + ty) * VOC + c];
    float* o1 = &outp[((size_t)(mA + 1) * TYD + ty) * VOC + c];
    float* o2 = &outp[((size_t)(mA + 2) * TYD + ty) * VOC + c];
    float* o3 = &outp[((size_t)(mA + 3) * TYD + ty) * VOC + c];
    *(float4*)o0 = make_float4(r0[0] + bv.x, r0[1] + bv.y, r0[2] + bv.z, r0[3] + bv.w);
    *(float4*)o1 = make_float4(r1[0] + bv.x, r1[1] + bv.y, r1[2] + bv.z, r1[3] + bv.w);
    *(float4*)o2 = make_float4(r2[0] + bv.x, r2[1] + bv.y, r2[2] + bv.z, r2[3] + bv.w);
    *(float4*)o3 = make_float4(r3[0] + bv.x, r3[1] + bv.y, r3[2] + bv.z, r3[3] + bv.w);
}

// ---------------- launch ----------------
extern "C" void kernel_launch(void* const* d_in, const int* in_sizes, int n_in,
                              void* d_out, int out_size)
{
    const float* X     = (const float*)d_in[0];
    const float* Wih_f = (const float*)d_in[1];
    const float* Whh_f = (const float*)d_in[2];
    const float* b_f   = (const float*)d_in[3];
    const float* Wih_b = (const float*)d_in[4];
    const float* Whh_b = (const float*)d_in[5];
    const float* b_b   = (const float*)d_in[6];
    const float* W1    = (const float*)d_in[7];
    const float* b1    = (const float*)d_in[8];
    const float* W2    = (const float*)d_in[9];
    const float* b2    = (const float*)d_in[10];
    const float* Wc_ih = (const float*)d_in[11];
    const float* Wc_hh = (const float*)d_in[12];
    const float* bc    = (const float*)d_in[13];
    const float* Wfc   = (const float*)d_in[14];
    const float* bfc   = (const float*)d_in[15];
    float* outp = (float*)d_out;

    const int LSTM_SMEM = (256 * 128 + 256 * 64 + 16 * 68) * 4;   // 200,960 B

    static int smem_set = 0;
    if (!smem_set) {
        cudaFuncSetAttribute(lstm_all_kernel,
                             cudaFuncAttributeMaxDynamicSharedMemorySize, LSTM_SMEM);
        smem_set = 1;
    }

    zero_bar_kernel<<<1, 256>>>();
    init_dec_kernel<<<512, 256>>>();
    xproj_kernel<<<dim3(16, 1024, 2), 256>>>(X, Wih_f, b_f, Wih_b, b_b);
    lstm_all_kernel<<<dim3(16, 4, 2), 128, LSTM_SMEM>>>(Whh_f, Whh_b);
    ea_kernel<<<256, 256>>>(W1);

    int pin = 0;
    for (int ty = 0; ty < TYD; ty++) {
        attention_kernel<<<MB, 256>>>(W1, b1, W2, b2, pin);
        dec_cell_kernel<<<dim3(32, 4), 256>>>(Wc_ih, Wc_hh, bc, pin);
        fc_kernel<<<dim3(16, 4), 256>>>(Wfc, bfc, outp, 1 - pin, ty);
        pin = 1 - pin;
    }
}

// round 10
// speedup vs baseline: 1.0252x; 1.0252x over previous
#include <cuda_runtime.h>
#include <cuda_bf16.h>
#include <math.h>

#define MB   256
#define TX   256
#define FDIM 128
#define NA   256
#define NS   512
#define VOC  1024
#define AH   10
#define TYD  10

// ---------------- scratch ----------------
__device__ float    g_gin[2][TX][MB][4 * NA];   // [m][g*256+u]
__device__ float    g_a[TX][MB][NS];
__device__ unsigned g_abf[TX][MB][NS / 2];      // bf16x2-packed copy of g_a
__device__ float    g_hT[2][2][NA][MB];         // [dir][t&1][u][m] double-buffered
__device__ float    g_Ea[MB][TX][AH];
__device__ float    g_ctx[MB][NS];
__device__ float    g_sbuf[2][MB][NS];
__device__ float    g_cdec[MB][NS];
__device__ unsigned g_bar[16][32];              // padded: one counter per 128B

__device__ __forceinline__ float sigf(float x) { return 1.f / (1.f + expf(-x)); }
__device__ __forceinline__ float fsig(float x) { return __fdividef(1.f, 1.f + __expf(-x)); }
__device__ __forceinline__ float ftanh(float x) { return 1.f - __fdividef(2.f, __expf(2.f * x) + 1.f); }

#define FMA2(acc, a, b) asm("fma.rn.f32x2 %0, %1, %2, %0;" : "+l"(acc) : "l"(a), "l"(b))
#define PACK2(d, lo, hi) asm("mov.b64 %0, {%1, %2};" : "=l"(d) : "f"(lo), "f"(hi))
#define UNPACK2(lo, hi, v) asm("mov.b64 {%0, %1}, %2;" : "=f"(lo), "=f"(hi) : "l"(v))

__global__ void zero_bar_kernel()
{
    int i = blockIdx.x * 256 + threadIdx.x;
    if (i < 512) ((unsigned*)g_bar)[i] = 0u;
}

__global__ void init_dec_kernel()
{
    int i = blockIdx.x * 256 + threadIdx.x;
    if (i < MB * NS) {
        (&g_sbuf[0][0][0])[i] = 0.f;
        (&g_cdec[0][0])[i] = 0.f;
    }
}

// ---------------- encoder input projection (f32x2): Gin = X @ Wih^T + b ----------------
__global__ void xproj_kernel(const float* __restrict__ X,
                             const float* __restrict__ Wf, const float* __restrict__ bf,
                             const float* __restrict__ Wb, const float* __restrict__ bb)
{
    int d = blockIdx.z;
    const float* W    = d ? Wb : Wf;
    const float* bias = d ? bb : bf;
    int col0 = blockIdx.x * 64;
    int row0 = blockIdx.y * 64;
    int t  = row0 >> 8;
    int m0 = row0 & 255;
    int xt = d ? (TX - 1 - t) : t;

    __shared__ float As[16][68];
    __shared__ float Bs[16][132];
    int tid = threadIdx.x;
    int ry = tid >> 4, rx = tid & 15;

    unsigned long long acc2[2][4];
    #pragma unroll
    for (int p = 0; p < 2; p++)
        #pragma unroll
        for (int j = 0; j < 4; j++) acc2[p][j] = 0ull;

    int lr = tid >> 2;
    int lk4 = (tid & 3) * 4;

    for (int k0 = 0; k0 < FDIM; k0 += 16) {
        float4 av = *(const float4*)(X + ((size_t)(m0 + lr) * TX + xt) * FDIM + k0 + lk4);
        As[lk4 + 0][lr] = av.x; As[lk4 + 1][lr] = av.y;
        As[lk4 + 2][lr] = av.z; As[lk4 + 3][lr] = av.w;
        float4 bv = *(const float4*)(W + (size_t)(col0 + lr) * FDIM + k0 + lk4);
        float vv[4] = {bv.x, bv.y, bv.z, bv.w};
        #pragma unroll
        for (int j = 0; j < 4; j++)
            *(float2*)&Bs[lk4 + j][lr * 2] = make_float2(vv[j], vv[j]);
        __syncthreads();
        #pragma unroll
        for (int kk = 0; kk < 16; kk++) {
            ulonglong2 ap = *(const ulonglong2*)&As[kk][ry * 4];
            ulonglong2 w0 = *(const ulonglong2*)&Bs[kk][rx * 8];
            ulonglong2 w1 = *(const ulonglong2*)&Bs[kk][rx * 8 + 4];
            FMA2(acc2[0][0], ap.x, w0.x); FMA2(acc2[0][1], ap.x, w0.y);
            FMA2(acc2[0][2], ap.x, w1.x); FMA2(acc2[0][3], ap.x, w1.y);
            FMA2(acc2[1][0], ap.y, w0.x); FMA2(acc2[1][1], ap.y, w0.y);
            FMA2(acc2[1][2], ap.y, w1.x); FMA2(acc2[1][3], ap.y, w1.y);
        }
        __syncthreads();
    }

    int c = col0 + rx * 4;
    float4 bv = *(const float4*)&bias[c];
    float r0[4], r1[4], r2[4], r3[4];
    UNPACK2(r0[0], r1[0], acc2[0][0]); UNPACK2(r0[1], r1[1], acc2[0][1]);
    UNPACK2(r0[2], r1[2], acc2[0][2]); UNPACK2(r0[3], r1[3], acc2[0][3]);
    UNPACK2(r2[0], r3[0], acc2[1][0]); UNPACK2(r2[1], r3[1], acc2[1][1]);
    UNPACK2(r2[2], r3[2], acc2[1][2]); UNPACK2(r2[3], r3[3], acc2[1][3]);
    float* o0 = &g_gin[d][t][m0 + ry * 4 + 0][c];
    float* o1 = &g_gin[d][t][m0 + ry * 4 + 1][c];
    float* o2 = &g_gin[d][t][m0 + ry * 4 + 2][c];
    float* o3 = &g_gin[d][t][m0 + ry * 4 + 3][c];
    *(float4*)o0 = make_float4(r0[0] + bv.x, r0[1] + bv.y, r0[2] + bv.z, r0[3] + bv.w);
    *(float4*)o1 = make_float4(r1[0] + bv.x, r1[1] + bv.y, r1[2] + bv.z, r1[3] + bv.w);
    *(float4*)o2 = make_float4(r2[0] + bv.x, r2[1] + bv.y, r2[2] + bv.z, r2[3] + bv.w);
    *(float4*)o3 = make_float4(r3[0] + bv.x, r3[1] + bv.y, r3[2] + bv.z, r3[3] + bv.w);
}

// ---------------- persistent recurrence: 8-CTA sync groups ----------------
// grid (8 u-CTAs, 8 m-tiles, 2 dirs) = 128 CTAs, 128 threads.
// CTA: 32 units (u0 = bx*32) x 4 gates = 128 cols (natural f32x2 col pairs), 32 m (m0 = by*32).
// thread (mq 0..7, cq 0..15): 4 m  x  8 cols (= 2 units, full gates).
// Ws[256][128]: col = ulocal*4+g, natural pairs {i,f},{g,o}. As[256][68]: h dup pairs.
__global__ void __launch_bounds__(128, 1) lstm_all_kernel(const float* __restrict__ Whf,
                                                          const float* __restrict__ Whb)
{
    extern __shared__ float sm[];
    float* Ws = sm;                  // 256*128 = 128 KB
    float* As = sm + 256 * 128;      // 256*68  = 69.6 KB (dup pairs, 32 m)
    float* Hs = As + 256 * 68;       // 32*36   = 4.6 KB staging [ulocal][m]

    int d = blockIdx.z;
    const float* W = d ? Whb : Whf;
    int u0 = blockIdx.x * 32;
    int m0 = blockIdx.y * 32;
    int tid = threadIdx.x;
    int mq = tid >> 4, cq = tid & 15;
    unsigned* barp = &g_bar[d * 8 + blockIdx.y][0];

    // one-time Ws fill: thread tid owns col = tid (ulocal = tid>>2, g = tid&3)
    {
        int ulocal = tid >> 2, g = tid & 3;
        const float* src = &W[(size_t)(g * NA + u0 + ulocal) * NA];
        for (int k4 = 0; k4 < 64; k4++) {
            float4 v = *(const float4*)(src + k4 * 4);
            Ws[(k4 * 4 + 0) * 128 + tid] = v.x;
            Ws[(k4 * 4 + 1) * 128 + tid] = v.y;
            Ws[(k4 * 4 + 2) * 128 + tid] = v.z;
            Ws[(k4 * 4 + 3) * 128 + tid] = v.w;
        }
    }

    float cst[2][4];
    #pragma unroll
    for (int uu = 0; uu < 2; uu++)
        #pragma unroll
        for (int mi = 0; mi < 4; mi++) cst[uu][mi] = 0.f;

    // gin prefetch t=0: per thread 4m x 2units x 4gates
    float rg[4][2][4];
    {
        const float* gb = &g_gin[d][0][0][0];
        #pragma unroll
        for (int mi = 0; mi < 4; mi++) {
            int m = m0 + mq * 4 + mi;
            #pragma unroll
            for (int uu = 0; uu < 2; uu++) {
                int u = u0 + cq * 2 + uu;
                #pragma unroll
                for (int g = 0; g < 4; g++)
                    rg[mi][uu][g] = gb[(size_t)m * 1024 + g * 256 + u];
            }
        }
    }

    for (int t = 0; t < TX; t++) {
        // ---- As fill: h(t-1) for all 256 k, this CTA's 32 m (dup pairs) ----
        if (t == 0) {
            float4 z = make_float4(0.f, 0.f, 0.f, 0.f);
            for (int idx = tid; idx < 256 * 68 / 4; idx += 128)
                ((float4*)As)[idx] = z;
        } else {
            const float* hsrc = &g_hT[d][(t - 1) & 1][0][0];
            for (int idx = tid; idx < 2048; idx += 128) {
                int m4 = idx & 7;           // 8 groups of 4 m
                int k  = idx >> 3;
                float4 v = __ldcg((const float4*)&hsrc[(size_t)k * MB + m0 + m4 * 4]);
                float* dst = &As[k * 68 + m4 * 8];
                *(float4*)&dst[0] = make_float4(v.x, v.x, v.y, v.y);
                *(float4*)&dst[4] = make_float4(v.z, v.z, v.w, v.w);
            }
        }
        __syncthreads();

        // ---- accumulators: acc2[mi][cp], cp = col pair ----
        unsigned long long acc2[4][4];
        #pragma unroll
        for (int mi = 0; mi < 4; mi++)
            #pragma unroll
            for (int uu = 0; uu < 2; uu++) {
                PACK2(acc2[mi][uu * 2 + 0], rg[mi][uu][0], rg[mi][uu][1]);  // {i,f}
                PACK2(acc2[mi][uu * 2 + 1], rg[mi][uu][2], rg[mi][uu][3]);  // {g,o}
            }

        #pragma unroll 4
        for (int k = 0; k < NA; k++) {
            ulonglong2 aA = *(const ulonglong2*)&As[k * 68 + mq * 8];       // {m0,m0},{m1,m1}
            ulonglong2 aB = *(const ulonglong2*)&As[k * 68 + mq * 8 + 4];   // {m2,m2},{m3,m3}
            ulonglong2 wA = *(const ulonglong2*)&Ws[k * 128 + cq * 8];      // cp0, cp1
            ulonglong2 wB = *(const ulonglong2*)&Ws[k * 128 + cq * 8 + 4];  // cp2, cp3
            FMA2(acc2[0][0], aA.x, wA.x); FMA2(acc2[0][1], aA.x, wA.y);
            FMA2(acc2[0][2], aA.x, wB.x); FMA2(acc2[0][3], aA.x, wB.y);
            FMA2(acc2[1][0], aA.y, wA.x); FMA2(acc2[1][1], aA.y, wA.y);
            FMA2(acc2[1][2], aA.y, wB.x); FMA2(acc2[1][3], aA.y, wB.y);
            FMA2(acc2[2][0], aB.x, wA.x); FMA2(acc2[2][1], aB.x, wA.y);
            FMA2(acc2[2][2], aB.x, wB.x); FMA2(acc2[2][3], aB.x, wB.y);
            FMA2(acc2[3][0], aB.y, wA.x); FMA2(acc2[3][1], aB.y, wA.y);
            FMA2(acc2[3][2], aB.y, wB.x); FMA2(acc2[3][3], aB.y, wB.y);
        }

        // ---- gates + state; stage h into Hs[ulocal][m] ----
        #pragma unroll
        for (int uu = 0; uu < 2; uu++) {
            int ulocal = cq * 2 + uu;
            #pragma unroll
            for (int mi = 0; mi < 4; mi++) {
                float iv, fv, gv, ov;
                UNPACK2(iv, fv, acc2[mi][uu * 2 + 0]);
                UNPACK2(gv, ov, acc2[mi][uu * 2 + 1]);
                float cn = fsig(fv) * cst[uu][mi] + fsig(iv) * ftanh(gv);
                cst[uu][mi] = cn;
                Hs[ulocal * 36 + mq * 4 + mi] = fsig(ov) * ftanh(cn);
            }
        }
        __syncthreads();

        // ---- cooperative coalesced writes from Hs ----
        int tw = d ? (TX - 1 - t) : t;
        {
            float* hdst = &g_hT[d][t & 1][0][0];
            #pragma unroll
            for (int i = 0; i < 2; i++) {        // hT[u0+uu][m0..]: 32u x 8 m-quads
                int idx = tid + 128 * i;
                int uu = idx >> 3, m4 = idx & 7;
                float4 v = *(float4*)&Hs[uu * 36 + m4 * 4];
                *(float4*)&hdst[(size_t)(u0 + uu) * MB + m0 + m4 * 4] = v;
            }
            #pragma unroll
            for (int i = 0; i < 2; i++) {        // g_a[m][u]: 32m x 8 u-quads
                int idx = tid + 128 * i;
                int mm = idx >> 3, q = idx & 7;
                float4 v = make_float4(Hs[(q * 4 + 0) * 36 + mm],
                                       Hs[(q * 4 + 1) * 36 + mm],
                                       Hs[(q * 4 + 2) * 36 + mm],
                                       Hs[(q * 4 + 3) * 36 + mm]);
                *(float4*)&g_a[tw][m0 + mm][d * NA + u0 + q * 4] = v;
            }
            {                                     // bf16 pack: 32m x 4 chunks (8u each)
                int mm = tid >> 2, ch = tid & 3;
                unsigned w[4];
                #pragma unroll
                for (int j = 0; j < 4; j++) {
                    float f0 = Hs[(ch * 8 + 2 * j + 0) * 36 + mm];
                    float f1 = Hs[(ch * 8 + 2 * j + 1) * 36 + mm];
                    __nv_bfloat162 b = __float22bfloat162_rn(make_float2(f0, f1));
                    w[j] = *(unsigned*)&b;
                }
                *(uint4*)&g_abf[tw][m0 + mm][(d * NA + u0) / 2 + ch * 4] =
                    make_uint4(w[0], w[1], w[2], w[3]);
            }
        }

        if (t + 1 < TX) {
            // prefetch gin(t+1)
            const float* gb = &g_gin[d][t + 1][0][0];
            #pragma unroll
            for (int mi = 0; mi < 4; mi++) {
                int m = m0 + mq * 4 + mi;
                #pragma unroll
                for (int uu = 0; uu < 2; uu++) {
                    int u = u0 + cq * 2 + uu;
                    #pragma unroll
                    for (int g = 0; g < 4; g++)
                        rg[mi][uu][g] = gb[(size_t)m * 1024 + g * 256 + u];
                }
            }
            __threadfence();
            __syncthreads();
            if (tid == 0) {
                asm volatile("red.release.gpu.global.add.u32 [%0], %1;"
                             :: "l"(barp), "r"(1u) : "memory");
                unsigned tgt = 8u * (unsigned)(t + 1);
                unsigned v;
                do {
                    asm volatile("ld.acquire.gpu.global.u32 %0, [%1];"
                                 : "=r"(v) : "l"(barp) : "memory");
                } while (v < tgt);
            }
            __syncthreads();
        }
    }
}

// ---------------- hoisted attention energies: Ea = a @ W1a^T ----------------
__global__ void ea_kernel(const float* __restrict__ W1)
{
    __shared__ float W1t[512][AH];
    int tid = threadIdx.x;
    for (int i = tid; i < 512 * AH; i += 256) {
        int h = i / 512, k = i - h * 512;
        W1t[k][h] = W1[h * 1024 + k];
    }
    __syncthreads();
    int r = blockIdx.x * 256 + tid;
    const float* arow = &g_a[0][0][0] + (size_t)r * NS;
    float e[AH] = {};
    for (int k = 0; k < 512; k += 4) {
        float4 av = *(const float4*)(arow + k);
        #pragma unroll
        for (int h = 0; h < AH; h++)
            e[h] += av.x * W1t[k][h] + av.y * W1t[k + 1][h]
                  + av.z * W1t[k + 2][h] + av.w * W1t[k + 3][h];
    }
    int tt = r >> 8;
    int m = r & 255;
    float* eo = &g_Ea[m][tt][0];
    #pragma unroll
    for (int h = 0; h < AH; h++) eo[h] = e[h];
}

// ---------------- attention ----------------
__global__ void attention_kernel(const float* __restrict__ W1, const float* __restrict__ b1,
                                 const float* __restrict__ W2, const float* __restrict__ b2,
                                 int pin)
{
    int m = blockIdx.x;
    int tid = threadIdx.x;
    int lane = tid & 31, warp = tid >> 5;
    __shared__ float Ss[NS];
    __shared__ float EsSh[AH];
    __shared__ float alpha[TX];
    __shared__ float red[8];
    __shared__ float sh_mx, sh_sum;

    const float* s_in = &g_sbuf[pin][m][0];
    Ss[tid] = s_in[tid];
    Ss[tid + 256] = s_in[tid + 256];
    __syncthreads();

    for (int h = warp; h < AH; h += 8) {
        float p = 0.f;
        for (int k = lane; k < NS; k += 32)
            p += Ss[k] * W1[h * 1024 + 512 + k];
        #pragma unroll
        for (int o = 16; o; o >>= 1) p += __shfl_xor_sync(0xffffffffu, p, o);
        if (lane == 0) EsSh[h] = p + b1[h];
    }
    __syncthreads();

    float sc = b2[0];
    {
        const float* ea = &g_Ea[m][tid][0];
        #pragma unroll
        for (int h = 0; h < AH; h++)
            sc += W2[h] * tanhf(ea[h] + EsSh[h]);
    }
    sc = fmaxf(sc, 0.f);

    float v = sc;
    #pragma unroll
    for (int o = 16; o; o >>= 1) v = fmaxf(v, __shfl_xor_sync(0xffffffffu, v, o));
    if (lane == 0) red[warp] = v;
    __syncthreads();
    if (tid == 0) {
        float mx = red[0];
        #pragma unroll
        for (int i = 1; i < 8; i++) mx = fmaxf(mx, red[i]);
        sh_mx = mx;
    }
    __syncthreads();
    float ev = expf(sc - sh_mx);
    float sv = ev;
    #pragma unroll
    for (int o = 16; o; o >>= 1) sv += __shfl_xor_sync(0xffffffffu, sv, o);
    if (lane == 0) red[warp] = sv;
    __syncthreads();
    if (tid == 0) {
        float s = 0.f;
        #pragma unroll
        for (int i = 0; i < 8; i++) s += red[i];
        sh_sum = s;
    }
    __syncthreads();
    alpha[tid] = ev / sh_sum;
    __syncthreads();

    const unsigned* ab = &g_abf[0][m][0] + tid;
    float ax = 0.f, ay = 0.f;
    #pragma unroll 8
    for (int t2 = 0; t2 < TX; t2++) {
        unsigned p = ab[(size_t)t2 * MB * (NS / 2)];
        __nv_bfloat162 b2v = *(__nv_bfloat162*)&p;
        float2 vv = __bfloat1622float2(b2v);
        float al = alpha[t2];
        ax += al * vv.x;
        ay += al * vv.y;
    }
    g_ctx[m][2 * tid + 0] = ax;
    g_ctx[m][2 * tid + 1] = ay;
}

// ---------------- decoder LSTM cell (f32x2) ----------------
__global__ void dec_cell_kernel(const float* __restrict__ Wih, const float* __restrict__ Whh,
                                const float* __restrict__ bc, int pin)
{
    int u0 = blockIdx.x * 16;
    int m0 = blockIdx.y * 64;
    int tid = threadIdx.x;
    int ul = tid & 15, mg = tid >> 4;
    int u = u0 + ul;

    __shared__ float As[32][68];
    __shared__ float Ws[32][132];

    unsigned long long acc2[2][4];
    #pragma unroll
    for (int g = 0; g < 4; g++) {
        float b = bc[g * NS + u];
        PACK2(acc2[0][g], b, b);
        acc2[1][g] = acc2[0][g];
    }

    for (int ph = 0; ph < 2; ph++) {
        const float* Arow = ph ? &g_sbuf[pin][0][0] : &g_ctx[0][0];
        const float* W = ph ? Whh : Wih;
        for (int k0 = 0; k0 < NS; k0 += 32) {
            #pragma unroll
            for (int i = 0; i < 2; i++) {
                int lin = tid + 256 * i;
                int mm = lin >> 3, kq = lin & 7;
                float4 f = *(const float4*)&Arow[(size_t)(m0 + mm) * NS + k0 + kq * 4];
                As[kq * 4 + 0][mm] = f.x; As[kq * 4 + 1][mm] = f.y;
                As[kq * 4 + 2][mm] = f.z; As[kq * 4 + 3][mm] = f.w;
            }
            #pragma unroll
            for (int i = 0; i < 2; i++) {
                int lin = tid + 256 * i;
                int r = lin >> 3, kq = lin & 7;
                int uu = r >> 2, g = r & 3;
                float4 f = *(const float4*)&W[(size_t)(g * NS + u0 + uu) * NS + k0 + kq * 4];
                float vv[4] = {f.x, f.y, f.z, f.w};
                #pragma unroll
                for (int j = 0; j < 4; j++)
                    *(float2*)&Ws[kq * 4 + j][r * 2] = make_float2(vv[j], vv[j]);
            }
            __syncthreads();
            #pragma unroll 8
            for (int kk = 0; kk < 32; kk++) {
                ulonglong2 ap = *(const ulonglong2*)&As[kk][mg * 4];
                ulonglong2 wA = *(const ulonglong2*)&Ws[kk][ul * 8];
                ulonglong2 wB = *(const ulonglong2*)&Ws[kk][ul * 8 + 4];
                FMA2(acc2[0][0], ap.x, wA.x); FMA2(acc2[0][1], ap.x, wA.y);
                FMA2(acc2[0][2], ap.x, wB.x); FMA2(acc2[0][3], ap.x, wB.y);
                FMA2(acc2[1][0], ap.y, wA.x); FMA2(acc2[1][1], ap.y, wA.y);
                FMA2(acc2[1][2], ap.y, wB.x); FMA2(acc2[1][3], ap.y, wB.y);
            }
            __syncthreads();
        }
    }

    #pragma unroll
    for (int p = 0; p < 2; p++) {
        float i0, i1, f0, f1, g0, g1, o0, o1;
        UNPACK2(i0, i1, acc2[p][0]);
        UNPACK2(f0, f1, acc2[p][1]);
        UNPACK2(g0, g1, acc2[p][2]);
        UNPACK2(o0, o1, acc2[p][3]);
        {
            int m = m0 + mg * 4 + 2 * p;
            float co = g_cdec[m][u];
            float cn = sigf(f0) * co + sigf(i0) * tanhf(g0);
            g_cdec[m][u] = cn;
            g_sbuf[1 - pin][m][u] = sigf(o0) * tanhf(cn);
        }
        {
            int m = m0 + mg * 4 + 2 * p + 1;
            float co = g_cdec[m][u];
            float cn = sigf(f1) * co + sigf(i1) * tanhf(g1);
            g_cdec[m][u] = cn;
            g_sbuf[1 - pin][m][u] = sigf(o1) * tanhf(cn);
        }
    }
}

// ---------------- output projection (f32x2) ----------------
__global__ void fc_kernel(const float* __restrict__ Wfc, const float* __restrict__ bfc,
                          float* __restrict__ outp, int ps, int ty)
{
    int col0 = blockIdx.x * 64;
    int m0 = blockIdx.y * 64;
    int tid = threadIdx.x;
    int ry = tid >> 4, rx = tid & 15;

    __shared__ float As[16][68];
    __shared__ float Bs[16][132];

    unsigned long long acc2[2][4];
    #pragma unroll
    for (int p = 0; p < 2; p++)
        #pragma unroll
        for (int j = 0; j < 4; j++) acc2[p][j] = 0ull;

    int lr = tid >> 2;
    int lk4 = (tid & 3) * 4;
    const float* S = &g_sbuf[ps][0][0];

    for (int k0 = 0; k0 < NS; k0 += 16) {
        float4 av = *(const float4*)(S + (size_t)(m0 + lr) * NS + k0 + lk4);
        As[lk4 + 0][lr] = av.x; As[lk4 + 1][lr] = av.y;
        As[lk4 + 2][lr] = av.z; As[lk4 + 3][lr] = av.w;
        float4 bv = *(const float4*)(Wfc + (size_t)(col0 + lr) * NS + k0 + lk4);
        float vv[4] = {bv.x, bv.y, bv.z, bv.w};
        #pragma unroll
        for (int j = 0; j < 4; j++)
            *(float2*)&Bs[lk4 + j][lr * 2] = make_float2(vv[j], vv[j]);
        __syncthreads();
        #pragma unroll
        for (int kk = 0; kk < 16; kk++) {
            ulonglong2 ap = *(const ulonglong2*)&As[kk][ry * 4];
            ulonglong2 w0 = *(const ulonglong2*)&Bs[kk][rx * 8];
            ulonglong2 w1 = *(const ulonglong2*)&Bs[kk][rx * 8 + 4];
            FMA2(acc2[0][0], ap.x, w0.x); FMA2(acc2[0][1], ap.x, w0.y);
            FMA2(acc2[0][2], ap.x, w1.x); FMA2(acc2[0][3], ap.x, w1.y);
            FMA2(acc2[1][0], ap.y, w0.x); FMA2(acc2[1][1], ap.y, w0.y);
            FMA2(acc2[1][2], ap.y, w1.x); FMA2(acc2[1][3], ap.y, w1.y);
        }
        __syncthreads();
    }

    int c = col0 + rx * 4;
    float4 bv = *(const float4*)&bfc[c];
    float r0[4], r1[4], r2[4], r3[4];
    UNPACK2(r0[0], r1[0], acc2[0][0]); UNPACK2(r0[1], r1[1], acc2[0][1]);
    UNPACK2(r0[2], r1[2], acc2[0][2]); UNPACK2(r0[3], r1[3], acc2[0][3]);
    UNPACK2(r2[0], r3[0], acc2[1][0]); UNPACK2(r2[1], r3[1], acc2[1][1]);
    UNPACK2(r2[2], r3[2], acc2[1][2]); UNPACK2(r2[3], r3[3], acc2[1][3]);
    int mA = m0 + ry * 4;
    float* o0 = &outp[((size_t)(mA + 0) * TYD + ty) * VOC + c];
    float* o1 = &outp[((size_t)(mA + 1) * TYD + ty) * VOC + c];
    float* o2 = &outp[((size_t)(mA + 2) * TYD + ty) * VOC + c];
    float* o3 = &outp[((size_t)(mA + 3) * TYD + ty) * VOC + c];
    *(float4*)o0 = make_float4(r0[0] + bv.x, r0[1] + bv.y, r0[2] + bv.z, r0[3] + bv.w);
    *(float4*)o1 = make_float4(r1[0] + bv.x, r1[1] + bv.y, r1[2] + bv.z, r1[3] + bv.w);
    *(float4*)o2 = make_float4(r2[0] + bv.x, r2[1] + bv.y, r2[2] + bv.z, r2[3] + bv.w);
    *(float4*)o3 = make_float4(r3[0] + bv.x, r3[1] + bv.y, r3[2] + bv.z, r3[3] + bv.w);
}

// ---------------- launch ----------------
extern "C" void kernel_launch(void* const* d_in, const int* in_sizes, int n_in,
                              void* d_out, int out_size)
{
    const float* X     = (const float*)d_in[0];
    const float* Wih_f = (const float*)d_in[1];
    const float* Whh_f = (const float*)d_in[2];
    const float* b_f   = (const float*)d_in[3];
    const float* Wih_b = (const float*)d_in[4];
    const float* Whh_b = (const float*)d_in[5];
    const float* b_b   = (const float*)d_in[6];
    const float* W1    = (const float*)d_in[7];
    const float* b1    = (const float*)d_in[8];
    const float* W2    = (const float*)d_in[9];
    const float* b2    = (const float*)d_in[10];
    const float* Wc_ih = (const float*)d_in[11];
    const float* Wc_hh = (const float*)d_in[12];
    const float* bc    = (const float*)d_in[13];
    const float* Wfc   = (const float*)d_in[14];
    const float* bfc   = (const float*)d_in[15];
    float* outp = (float*)d_out;

    const int LSTM_SMEM = (256 * 128 + 256 * 68 + 32 * 36) * 4;   // 205,312 B

    static int smem_set = 0;
    if (!smem_set) {
        cudaFuncSetAttribute(lstm_all_kernel,
                             cudaFuncAttributeMaxDynamicSharedMemorySize, LSTM_SMEM);
        smem_set = 1;
    }

    zero_bar_kernel<<<2, 256>>>();
    init_dec_kernel<<<512, 256>>>();
    xproj_kernel<<<dim3(16, 1024, 2), 256>>>(X, Wih_f, b_f, Wih_b, b_b);
    lstm_all_kernel<<<dim3(8, 8, 2), 128, LSTM_SMEM>>>(Whh_f, Whh_b);
    ea_kernel<<<256, 256>>>(W1);

    int pin = 0;
    for (int ty = 0; ty < TYD; ty++) {
        attention_kernel<<<MB, 256>>>(W1, b1, W2, b2, pin);
        dec_cell_kernel<<<dim3(32, 4), 256>>>(Wc_ih, Wc_hh, bc, pin);
        fc_kernel<<<dim3(16, 4), 256>>>(Wfc, bfc, outp, 1 - pin, ty);
        pin = 1 - pin;
    }
}